// round 16
// baseline (speedup 1.0000x reference)
#include <cuda_runtime.h>
#include <cuda_fp16.h>
#include <cuda_bf16.h>
#include <cstdint>

#define DOUT 128
#define N_MAX 50000
#define E_MAX 800000
#define CHUNK 4096
#define AS 136   // A tile stride (halves)
#define WS 136   // W tile stride (halves)

// Scratch (device globals — no allocation allowed)
__device__ __align__(16) __half g_zh[(size_t)N_MAX * DOUT];
__device__ float  g_ssrc[N_MAX];
__device__ float  g_sdst[N_MAX];
__device__ int    g_cnt[N_MAX];
__device__ int    g_off[N_MAX + 1];
__device__ int    g_rank[E_MAX];
__device__ int    g_packed[E_MAX];

// ---------------------------------------------------------------------------
// m16n8k16 bf16 MMA (plain PTX, sm_80+; no arch-'a' features)
// ---------------------------------------------------------------------------
__device__ __forceinline__ void mma16816(float* d, const uint32_t* a, const uint32_t* b) {
    asm volatile("mma.sync.aligned.m16n8k16.row.col.f32.bf16.bf16.f32 "
        "{%0,%1,%2,%3}, {%4,%5,%6,%7}, {%8,%9}, {%0,%1,%2,%3};"
        : "+f"(d[0]), "+f"(d[1]), "+f"(d[2]), "+f"(d[3])
        : "r"(a[0]), "r"(a[1]), "r"(a[2]), "r"(a[3]), "r"(b[0]), "r"(b[1]));
}

// k-permutation within each 16-wide group so that the two B fragment regs
// (halves kq,kq+1 and kq+8,kq+9) sit in ONE aligned 8-byte word:
// memory order per group: [0,1,8,9, 2,3,10,11, 4,5,12,13, 6,7,14,15]
__device__ __forceinline__ int kperm(int k) {
    return (k & ~15) + ((k & 6) >> 1) * 4 + ((k >> 3) & 1) * 2 + (k & 1);
}

// ---------------------------------------------------------------------------
// z = h @ W via bf16-split tensor-core MMA (hi*hi + hi*lo + lo*hi, f32 acc).
// W smem is k-permuted so each B fragment is one LDS.64 (B-load instrs halved).
// Epilogue: scores via quad-reduce, z stored fp16.
// ---------------------------------------------------------------------------
__global__ void __launch_bounds__(256)
gemm_kernel(const float* __restrict__ h, const float* __restrict__ W,
            const float* __restrict__ attn, int N) {
    extern __shared__ char smem[];
    __nv_bfloat16* Ah = (__nv_bfloat16*)smem;          // [128][AS]
    __nv_bfloat16* Al = Ah + 128 * AS;
    __nv_bfloat16* Wh = Al + 128 * AS;                 // Wt[n][kperm]
    __nv_bfloat16* Wl = Wh + 128 * WS;
    float* s_attn = (float*)(Wl + 128 * WS);           // [256]

    int tid = threadIdx.x;
    s_attn[tid] = attn[tid];

    int rowbase = blockIdx.x * 128;
    const float4* h4 = (const float4*)h;
#pragma unroll
    for (int it = 0; it < 16; it++) {
        int idx = it * 256 + tid;          // 4096 float4
        int r = idx >> 5, c4 = idx & 31;
        float4 v = make_float4(0.f, 0.f, 0.f, 0.f);
        if (rowbase + r < N) v = h4[(size_t)(rowbase + r) * 32 + c4];
        int k = c4 * 4;
        float vv[4] = {v.x, v.y, v.z, v.w};
#pragma unroll
        for (int j = 0; j < 4; j++) {
            __nv_bfloat16 hb = __float2bfloat16_rn(vv[j]);
            Ah[r * AS + k + j] = hb;
            Al[r * AS + k + j] = __float2bfloat16_rn(vv[j] - __bfloat162float(hb));
        }
    }
    const float4* W4 = (const float4*)W;
#pragma unroll
    for (int it = 0; it < 16; it++) {
        int idx = it * 256 + tid;
        int k = idx >> 5, c4 = idx & 31;   // k = W row; 4 consecutive n
        float4 v = W4[(size_t)k * 32 + c4];
        int n = c4 * 4;
        int kp = kperm(k);
        float vv[4] = {v.x, v.y, v.z, v.w};
#pragma unroll
        for (int j = 0; j < 4; j++) {
            __nv_bfloat16 hb = __float2bfloat16_rn(vv[j]);
            Wh[(n + j) * WS + kp] = hb;
            Wl[(n + j) * WS + kp] = __float2bfloat16_rn(vv[j] - __bfloat162float(hb));
        }
    }
    __syncthreads();

    int wid = tid >> 5, lane = tid & 31;
    int r0 = wid * 16;
    int arow = r0 + (lane >> 2);       // tile-local row for d0/d1
    int kq = (lane & 3) * 2;

    float D[16][4];
#pragma unroll
    for (int nt = 0; nt < 16; nt++) {
        D[nt][0] = 0.f; D[nt][1] = 0.f; D[nt][2] = 0.f; D[nt][3] = 0.f;
    }

#pragma unroll
    for (int ks = 0; ks < 8; ks++) {
        int k0 = ks * 16;
        uint32_t Ahf[4], Alf[4];
        Ahf[0] = *(const uint32_t*)&Ah[arow * AS + k0 + kq];
        Ahf[1] = *(const uint32_t*)&Ah[(arow + 8) * AS + k0 + kq];
        Ahf[2] = *(const uint32_t*)&Ah[arow * AS + k0 + kq + 8];
        Ahf[3] = *(const uint32_t*)&Ah[(arow + 8) * AS + k0 + kq + 8];
        Alf[0] = *(const uint32_t*)&Al[arow * AS + k0 + kq];
        Alf[1] = *(const uint32_t*)&Al[(arow + 8) * AS + k0 + kq];
        Alf[2] = *(const uint32_t*)&Al[arow * AS + k0 + kq + 8];
        Alf[3] = *(const uint32_t*)&Al[(arow + 8) * AS + k0 + kq + 8];
#pragma unroll
        for (int nt = 0; nt < 16; nt++) {
            int bn = nt * 8 + (lane >> 2);
            // permuted layout: both fragment regs in one 8B word
            uint2 bh = *(const uint2*)&Wh[bn * WS + k0 + kq * 2];
            uint2 bl = *(const uint2*)&Wl[bn * WS + k0 + kq * 2];
            mma16816(D[nt], Ahf, (const uint32_t*)&bh);
            mma16816(D[nt], Ahf, (const uint32_t*)&bl);
            mma16816(D[nt], Alf, (const uint32_t*)&bh);
        }
    }

    // ---- epilogue: scores + fp16 z ----
    float ps0 = 0.f, pd0 = 0.f, ps1 = 0.f, pd1 = 0.f;
#pragma unroll
    for (int nt = 0; nt < 16; nt++) {
        int c = nt * 8 + kq;
        float a0 = s_attn[c], a1 = s_attn[c + 1];
        float b0 = s_attn[128 + c], b1 = s_attn[128 + c + 1];
        ps0 += D[nt][0] * a0 + D[nt][1] * a1;
        pd0 += D[nt][0] * b0 + D[nt][1] * b1;
        ps1 += D[nt][2] * a0 + D[nt][3] * a1;
        pd1 += D[nt][2] * b0 + D[nt][3] * b1;
    }
#pragma unroll
    for (int o = 1; o < 4; o <<= 1) {
        ps0 += __shfl_xor_sync(0xffffffffu, ps0, o);
        pd0 += __shfl_xor_sync(0xffffffffu, pd0, o);
        ps1 += __shfl_xor_sync(0xffffffffu, ps1, o);
        pd1 += __shfl_xor_sync(0xffffffffu, pd1, o);
    }
    int row0 = rowbase + arow;
    int row1 = row0 + 8;
    if ((lane & 3) == 0) {
        if (row0 < N) { g_ssrc[row0] = ps0; g_sdst[row0] = pd0; }
        if (row1 < N) { g_ssrc[row1] = ps1; g_sdst[row1] = pd1; }
    }
    if (row0 < N) {
#pragma unroll
        for (int nt = 0; nt < 16; nt++) {
            __half2 p = __floats2half2_rn(D[nt][0], D[nt][1]);
            *(__half2*)&g_zh[(size_t)row0 * 128 + nt * 8 + kq] = p;
        }
    }
    if (row1 < N) {
#pragma unroll
        for (int nt = 0; nt < 16; nt++) {
            __half2 p = __floats2half2_rn(D[nt][2], D[nt][3]);
            *(__half2*)&g_zh[(size_t)row1 * 128 + nt * 8 + kq] = p;
        }
    }
}

// ---------------------------------------------------------------------------
// Edge-index chain (parallel stream; independent of gemm)
// ---------------------------------------------------------------------------
__global__ void clear_cnt(int N) {
    int i = blockIdx.x * blockDim.x + threadIdx.x;
    if (i < N) g_cnt[i] = 0;
}

__global__ void hist_kernel(const int* __restrict__ dst, int E) {
    int i = blockIdx.x * blockDim.x + threadIdx.x;
    if (i < E) g_rank[i] = atomicAdd(&g_cnt[dst[i]], 1);
}

// Single-kernel exclusive scan: block b redundantly reduces [0, b*CHUNK),
// then scans its own CHUNK. No inter-block protocol.
__global__ void __launch_bounds__(256)
scan_kernel(int N) {
    __shared__ int sh[9];
    int b = blockIdx.x, t = threadIdx.x;
    int lane = t & 31, wid = t >> 5;
    int base = b * CHUNK;

    int pre = 0;
    const int4* c4 = (const int4*)g_cnt;
    for (int i = t; i * 4 < base; i += 256) {
        int4 v = c4[i];
        pre += v.x + v.y + v.z + v.w;
    }
#pragma unroll
    for (int o = 16; o > 0; o >>= 1) pre += __shfl_xor_sync(0xffffffffu, pre, o);
    if (lane == 0) sh[wid] = pre;
    __syncthreads();
    if (t == 0) {
        int s = 0;
#pragma unroll
        for (int i = 0; i < 8; i++) s += sh[i];
        sh[8] = s;
    }
    __syncthreads();
    int pretot = sh[8];
    __syncthreads();

    int tbase = base + t * 16;
    int vals[16];
    int tsum = 0;
    if (tbase + 16 <= N) {
#pragma unroll
        for (int j = 0; j < 16; j += 4) {
            int4 v = c4[(tbase + j) >> 2];
            vals[j] = v.x; vals[j+1] = v.y; vals[j+2] = v.z; vals[j+3] = v.w;
            tsum += v.x + v.y + v.z + v.w;
        }
    } else {
#pragma unroll
        for (int j = 0; j < 16; j++) {
            int idx = tbase + j;
            vals[j] = (idx < N) ? g_cnt[idx] : 0;
            tsum += vals[j];
        }
    }

    int x = tsum;
#pragma unroll
    for (int o = 1; o < 32; o <<= 1) {
        int y = __shfl_up_sync(0xffffffffu, x, o);
        if (lane >= o) x += y;
    }
    if (lane == 31) sh[wid] = x;
    __syncthreads();
    if (t < 8) {
        int s = sh[t];
#pragma unroll
        for (int o = 1; o < 8; o <<= 1) {
            int y = __shfl_up_sync(0x000000ffu, s, o);
            if (t >= o) s += y;
        }
        sh[t] = s;
    }
    __syncthreads();

    int run = pretot + (wid ? sh[wid - 1] : 0) + x - tsum;
#pragma unroll
    for (int j = 0; j < 16; j++) {
        int idx = tbase + j;
        if (idx < N) g_off[idx] = run;
        run += vals[j];
    }
    if (t == 0 && b == gridDim.x - 1) g_off[N] = pretot + sh[7];
}

// Atomic-free scatter: pos = off[dst] + rank (rank captured in hist).
__global__ void scatter_kernel(const int* __restrict__ src, const int* __restrict__ dst,
                               const int* __restrict__ etype, int E) {
    int i = blockIdx.x * blockDim.x + threadIdx.x;
    if (i >= E) return;
    int pos = g_off[dst[i]] + g_rank[i];
    g_packed[pos] = src[i] | (etype[i] << 17);
}

// ---------------------------------------------------------------------------
// One warp per dst node, TWO edges per broadcast iteration (R12 best form).
// ---------------------------------------------------------------------------
__global__ void __launch_bounds__(256)
gather_kernel(const float* __restrict__ rel, float* __restrict__ out, int N) {
    int node = (blockIdx.x * blockDim.x + threadIdx.x) >> 5;
    int lane = threadIdx.x & 31;
    if (node >= N) return;

    int beg = g_off[node], end = g_off[node + 1];
    float sd = g_sdst[node];

    int hl = lane >> 4;          // which edge of the pair
    int c8 = lane & 15;          // col-octet (8 halves) this lane owns

    float acc[8];
#pragma unroll
    for (int j = 0; j < 8; j++) acc[j] = 0.f;
    float dsum = 0.f;
    const uint4* zh4 = (const uint4*)g_zh;   // 16 uint4 per row

    for (int base = beg; base < end; base += 32) {
        int idx = base + lane;
        float w = 0.f, exv = 0.f;
        int s = 0;
        if (idx < end) {
            int p = g_packed[idx];
            s = p & 131071;
            int et = p >> 17;
            float v = g_ssrc[s] + sd;
            float e = v > 0.f ? v : 0.01f * v;
            exv = __expf(e);
            w = (et == 0 ? 0.f : __ldg(&rel[et])) * exv;
        }
        dsum += exv;
        int cnt = min(32, end - base);
        int npair = (cnt + 1) >> 1;
#pragma unroll 4
        for (int t = 0; t < npair; t++) {
            int e = 2 * t + hl;   // may be == cnt on odd tail -> w there is 0
            float wi = __shfl_sync(0xffffffffu, w, e);
            int   si = __shfl_sync(0xffffffffu, s, e);
            uint4 raw = zh4[(size_t)si * 16 + c8];
            float2 f0 = __half22float2(*(__half2*)&raw.x);
            float2 f1 = __half22float2(*(__half2*)&raw.y);
            float2 f2 = __half22float2(*(__half2*)&raw.z);
            float2 f3 = __half22float2(*(__half2*)&raw.w);
            acc[0] += wi * f0.x; acc[1] += wi * f0.y;
            acc[2] += wi * f1.x; acc[3] += wi * f1.y;
            acc[4] += wi * f2.x; acc[5] += wi * f2.y;
            acc[6] += wi * f3.x; acc[7] += wi * f3.y;
        }
    }

#pragma unroll
    for (int o = 16; o > 0; o >>= 1)
        dsum += __shfl_xor_sync(0xffffffffu, dsum, o);
#pragma unroll
    for (int j = 0; j < 8; j++)
        acc[j] += __shfl_xor_sync(0xffffffffu, acc[j], 16);

    float inv = dsum > 0.f ? __frcp_rn(dsum) : 0.f;
    if (lane < 16) {
        float4* o4 = (float4*)(out + (size_t)node * DOUT + c8 * 8);
        o4[0] = make_float4(acc[0] * inv, acc[1] * inv, acc[2] * inv, acc[3] * inv);
        o4[1] = make_float4(acc[4] * inv, acc[5] * inv, acc[6] * inv, acc[7] * inv);
    }
}

// ---------------------------------------------------------------------------
extern "C" void kernel_launch(void* const* d_in, const int* in_sizes, int n_in,
                              void* d_out, int out_size) {
    const float* h    = (const float*)d_in[0];
    const float* W    = (const float*)d_in[1];
    const float* attn = (const float*)d_in[2];
    const float* rel  = (const float*)d_in[3];
    const int*   src  = (const int*)d_in[4];
    const int*   dst  = (const int*)d_in[5];
    const int*   et   = (const int*)d_in[6];
    float* out = (float*)d_out;

    int N = in_sizes[0] / DOUT;
    int E = in_sizes[4];
    int nblk = (N + CHUNK - 1) / CHUNK;
    int smem_bytes = 4 * 128 * AS * 2 + 256 * 4;   // 4 bf16 tiles + attn

    // Lazy one-time creation of side stream + events (host objects only; made
    // on the uncaptured correctness call, reused under capture). If creation
    // fails (e.g. transient driver state), fall back to serial single-stream.
    static cudaStream_t s2 = nullptr;
    static cudaEvent_t evFork = nullptr, evJoin = nullptr;
    static bool tried = false, have_fork = false, attr_set = false;
    if (!tried) {
        tried = true;
        if (cudaStreamCreateWithFlags(&s2, cudaStreamNonBlocking) == cudaSuccess &&
            cudaEventCreateWithFlags(&evFork, cudaEventDisableTiming) == cudaSuccess &&
            cudaEventCreateWithFlags(&evJoin, cudaEventDisableTiming) == cudaSuccess) {
            have_fork = true;
        }
    }
    if (!attr_set) {
        cudaFuncSetAttribute(gemm_kernel, cudaFuncAttributeMaxDynamicSharedMemorySize, smem_bytes);
        attr_set = true;
    }

    if (have_fork) {
        // Fork: edge-index chain on s2, gemm on the main (capturing) stream.
        // gemm submitted 4th so ncu's fixed capture slot profiles it.
        cudaEventRecord(evFork, 0);
        cudaStreamWaitEvent(s2, evFork, 0);

        clear_cnt<<<(N + 255) / 256, 256, 0, s2>>>(N);
        hist_kernel<<<(E + 255) / 256, 256, 0, s2>>>(dst, E);
        scan_kernel<<<nblk, 256, 0, s2>>>(N);

        gemm_kernel<<<(N + 127) / 128, 256, smem_bytes>>>(h, W, attn, N);

        scatter_kernel<<<(E + 255) / 256, 256, 0, s2>>>(src, dst, et, E);
        cudaEventRecord(evJoin, s2);

        cudaStreamWaitEvent(0, evJoin, 0);
    } else {
        clear_cnt<<<(N + 255) / 256, 256>>>(N);
        hist_kernel<<<(E + 255) / 256, 256>>>(dst, E);
        scan_kernel<<<nblk, 256>>>(N);
        gemm_kernel<<<(N + 127) / 128, 256, smem_bytes>>>(h, W, attn, N);
        scatter_kernel<<<(E + 255) / 256, 256>>>(src, dst, et, E);
    }

    gather_kernel<<<(N * 32 + 255) / 256, 256>>>(rel, out, N);
}

// round 17
// speedup vs baseline: 1.0871x; 1.0871x over previous
#include <cuda_runtime.h>
#include <cuda_fp16.h>
#include <cuda_bf16.h>
#include <cstdint>

#define DOUT 128
#define N_MAX 50000
#define E_MAX 800000
#define CHUNK 4096
#define AS 136   // A tile stride (halves)
#define WS 136   // W tile stride (halves)

// Scratch (device globals — no allocation allowed)
__device__ __align__(16) __half g_zh[(size_t)N_MAX * DOUT];
__device__ __align__(8) float g_ssrc2[2 * N_MAX];   // per-half partial scores
__device__ __align__(8) float g_sdst2[2 * N_MAX];
__device__ int    g_cnt[N_MAX];
__device__ int    g_off[N_MAX + 1];
__device__ int    g_rank[E_MAX];
__device__ int    g_packed[E_MAX];

// ---------------------------------------------------------------------------
// m16n8k16 bf16 MMA (plain PTX, sm_80+; no arch-'a' features)
// ---------------------------------------------------------------------------
__device__ __forceinline__ void mma16816(float* d, const uint32_t* a, const uint32_t* b) {
    asm volatile("mma.sync.aligned.m16n8k16.row.col.f32.bf16.bf16.f32 "
        "{%0,%1,%2,%3}, {%4,%5,%6,%7}, {%8,%9}, {%0,%1,%2,%3};"
        : "+f"(d[0]), "+f"(d[1]), "+f"(d[2]), "+f"(d[3])
        : "r"(a[0]), "r"(a[1]), "r"(a[2]), "r"(a[3]), "r"(b[0]), "r"(b[1]));
}

// ---------------------------------------------------------------------------
// z = h @ W via bf16-split tensor-core MMA (hi*hi + hi*lo + lo*hi, f32 acc).
// N SPLIT ACROSS BLOCKS: block = 128 rows x 64 cols, full K. Smem 103KB ->
// 2 blocks/SM (16 warps) vs previous 140KB/1-block. Scores are per-half
// partials (g_ssrc2/g_sdst2); gather sums the pair.
// ---------------------------------------------------------------------------
__global__ void __launch_bounds__(256)
gemm_kernel(const float* __restrict__ h, const float* __restrict__ W,
            const float* __restrict__ attn, int N) {
    extern __shared__ char smem[];
    __nv_bfloat16* Ah = (__nv_bfloat16*)smem;          // [128][AS]
    __nv_bfloat16* Al = Ah + 128 * AS;
    __nv_bfloat16* Wh = Al + 128 * AS;                 // Wt[n_local][k], 64 rows
    __nv_bfloat16* Wl = Wh + 64 * WS;
    float* s_attn = (float*)(Wl + 64 * WS);            // [256]

    int tid = threadIdx.x;
    s_attn[tid] = attn[tid];

    int bx = blockIdx.x;
    int rowbase = (bx >> 1) * 128;
    int half = bx & 1;
    int ncol0 = half * 64;

    const float4* h4 = (const float4*)h;
#pragma unroll
    for (int it = 0; it < 16; it++) {
        int idx = it * 256 + tid;          // 4096 float4
        int r = idx >> 5, c4 = idx & 31;
        float4 v = make_float4(0.f, 0.f, 0.f, 0.f);
        if (rowbase + r < N) v = h4[(size_t)(rowbase + r) * 32 + c4];
        int k = c4 * 4;
        float vv[4] = {v.x, v.y, v.z, v.w};
#pragma unroll
        for (int j = 0; j < 4; j++) {
            __nv_bfloat16 hb = __float2bfloat16_rn(vv[j]);
            Ah[r * AS + k + j] = hb;
            Al[r * AS + k + j] = __float2bfloat16_rn(vv[j] - __bfloat162float(hb));
        }
    }
    const float4* W4 = (const float4*)W;
#pragma unroll
    for (int it = 0; it < 8; it++) {
        int idx = it * 256 + tid;          // 2048 float4 (64-col half)
        int k = idx >> 4, c4 = idx & 15;
        float4 v = W4[(size_t)k * 32 + (ncol0 >> 2) + c4];
        int n = c4 * 4;                    // local n 0..63
        float vv[4] = {v.x, v.y, v.z, v.w};
#pragma unroll
        for (int j = 0; j < 4; j++) {
            __nv_bfloat16 hb = __float2bfloat16_rn(vv[j]);
            Wh[(n + j) * WS + k] = hb;
            Wl[(n + j) * WS + k] = __float2bfloat16_rn(vv[j] - __bfloat162float(hb));
        }
    }
    __syncthreads();

    int wid = tid >> 5, lane = tid & 31;
    int r0 = wid * 16;
    int arow = r0 + (lane >> 2);       // tile-local row for d0/d1
    int kq = (lane & 3) * 2;

    float D[8][4];
#pragma unroll
    for (int nt = 0; nt < 8; nt++) {
        D[nt][0] = 0.f; D[nt][1] = 0.f; D[nt][2] = 0.f; D[nt][3] = 0.f;
    }

#pragma unroll
    for (int ks = 0; ks < 8; ks++) {
        int k0 = ks * 16;
        uint32_t Ahf[4], Alf[4];
        Ahf[0] = *(const uint32_t*)&Ah[arow * AS + k0 + kq];
        Ahf[1] = *(const uint32_t*)&Ah[(arow + 8) * AS + k0 + kq];
        Ahf[2] = *(const uint32_t*)&Ah[arow * AS + k0 + kq + 8];
        Ahf[3] = *(const uint32_t*)&Ah[(arow + 8) * AS + k0 + kq + 8];
        Alf[0] = *(const uint32_t*)&Al[arow * AS + k0 + kq];
        Alf[1] = *(const uint32_t*)&Al[(arow + 8) * AS + k0 + kq];
        Alf[2] = *(const uint32_t*)&Al[arow * AS + k0 + kq + 8];
        Alf[3] = *(const uint32_t*)&Al[(arow + 8) * AS + k0 + kq + 8];
#pragma unroll
        for (int nt = 0; nt < 8; nt++) {
            int bn = nt * 8 + (lane >> 2);
            uint32_t Bh[2], Bl[2];
            Bh[0] = *(const uint32_t*)&Wh[bn * WS + k0 + kq];
            Bh[1] = *(const uint32_t*)&Wh[bn * WS + k0 + kq + 8];
            Bl[0] = *(const uint32_t*)&Wl[bn * WS + k0 + kq];
            Bl[1] = *(const uint32_t*)&Wl[bn * WS + k0 + kq + 8];
            mma16816(D[nt], Ahf, Bh);
            mma16816(D[nt], Ahf, Bl);
            mma16816(D[nt], Alf, Bh);
        }
    }

    // ---- epilogue: partial scores over this 64-col half + fp16 z ----
    float ps0 = 0.f, pd0 = 0.f, ps1 = 0.f, pd1 = 0.f;
#pragma unroll
    for (int nt = 0; nt < 8; nt++) {
        int c = ncol0 + nt * 8 + kq;
        float a0 = s_attn[c], a1 = s_attn[c + 1];
        float b0 = s_attn[128 + c], b1 = s_attn[128 + c + 1];
        ps0 += D[nt][0] * a0 + D[nt][1] * a1;
        pd0 += D[nt][0] * b0 + D[nt][1] * b1;
        ps1 += D[nt][2] * a0 + D[nt][3] * a1;
        pd1 += D[nt][2] * b0 + D[nt][3] * b1;
    }
#pragma unroll
    for (int o = 1; o < 4; o <<= 1) {
        ps0 += __shfl_xor_sync(0xffffffffu, ps0, o);
        pd0 += __shfl_xor_sync(0xffffffffu, pd0, o);
        ps1 += __shfl_xor_sync(0xffffffffu, ps1, o);
        pd1 += __shfl_xor_sync(0xffffffffu, pd1, o);
    }
    int row0 = rowbase + arow;
    int row1 = row0 + 8;
    if ((lane & 3) == 0) {
        if (row0 < N) { g_ssrc2[row0 * 2 + half] = ps0; g_sdst2[row0 * 2 + half] = pd0; }
        if (row1 < N) { g_ssrc2[row1 * 2 + half] = ps1; g_sdst2[row1 * 2 + half] = pd1; }
    }
    if (row0 < N) {
#pragma unroll
        for (int nt = 0; nt < 8; nt++) {
            __half2 p = __floats2half2_rn(D[nt][0], D[nt][1]);
            *(__half2*)&g_zh[(size_t)row0 * 128 + ncol0 + nt * 8 + kq] = p;
        }
    }
    if (row1 < N) {
#pragma unroll
        for (int nt = 0; nt < 8; nt++) {
            __half2 p = __floats2half2_rn(D[nt][2], D[nt][3]);
            *(__half2*)&g_zh[(size_t)row1 * 128 + ncol0 + nt * 8 + kq] = p;
        }
    }
}

// ---------------------------------------------------------------------------
// Edge-index chain (parallel stream; independent of gemm)
// ---------------------------------------------------------------------------
__global__ void clear_cnt(int N) {
    int i = blockIdx.x * blockDim.x + threadIdx.x;
    if (i < N) g_cnt[i] = 0;
}

__global__ void hist_kernel(const int* __restrict__ dst, int E) {
    int i = blockIdx.x * blockDim.x + threadIdx.x;
    if (i < E) g_rank[i] = atomicAdd(&g_cnt[dst[i]], 1);
}

// Single-kernel exclusive scan: block b redundantly reduces [0, b*CHUNK),
// then scans its own CHUNK. No inter-block protocol.
__global__ void __launch_bounds__(256)
scan_kernel(int N) {
    __shared__ int sh[9];
    int b = blockIdx.x, t = threadIdx.x;
    int lane = t & 31, wid = t >> 5;
    int base = b * CHUNK;

    int pre = 0;
    const int4* c4 = (const int4*)g_cnt;
    for (int i = t; i * 4 < base; i += 256) {
        int4 v = c4[i];
        pre += v.x + v.y + v.z + v.w;
    }
#pragma unroll
    for (int o = 16; o > 0; o >>= 1) pre += __shfl_xor_sync(0xffffffffu, pre, o);
    if (lane == 0) sh[wid] = pre;
    __syncthreads();
    if (t == 0) {
        int s = 0;
#pragma unroll
        for (int i = 0; i < 8; i++) s += sh[i];
        sh[8] = s;
    }
    __syncthreads();
    int pretot = sh[8];
    __syncthreads();

    int tbase = base + t * 16;
    int vals[16];
    int tsum = 0;
    if (tbase + 16 <= N) {
#pragma unroll
        for (int j = 0; j < 16; j += 4) {
            int4 v = c4[(tbase + j) >> 2];
            vals[j] = v.x; vals[j+1] = v.y; vals[j+2] = v.z; vals[j+3] = v.w;
            tsum += v.x + v.y + v.z + v.w;
        }
    } else {
#pragma unroll
        for (int j = 0; j < 16; j++) {
            int idx = tbase + j;
            vals[j] = (idx < N) ? g_cnt[idx] : 0;
            tsum += vals[j];
        }
    }

    int x = tsum;
#pragma unroll
    for (int o = 1; o < 32; o <<= 1) {
        int y = __shfl_up_sync(0xffffffffu, x, o);
        if (lane >= o) x += y;
    }
    if (lane == 31) sh[wid] = x;
    __syncthreads();
    if (t < 8) {
        int s = sh[t];
#pragma unroll
        for (int o = 1; o < 8; o <<= 1) {
            int y = __shfl_up_sync(0x000000ffu, s, o);
            if (t >= o) s += y;
        }
        sh[t] = s;
    }
    __syncthreads();

    int run = pretot + (wid ? sh[wid - 1] : 0) + x - tsum;
#pragma unroll
    for (int j = 0; j < 16; j++) {
        int idx = tbase + j;
        if (idx < N) g_off[idx] = run;
        run += vals[j];
    }
    if (t == 0 && b == gridDim.x - 1) g_off[N] = pretot + sh[7];
}

// Atomic-free scatter: pos = off[dst] + rank (rank captured in hist).
__global__ void scatter_kernel(const int* __restrict__ src, const int* __restrict__ dst,
                               const int* __restrict__ etype, int E) {
    int i = blockIdx.x * blockDim.x + threadIdx.x;
    if (i >= E) return;
    int pos = g_off[dst[i]] + g_rank[i];
    g_packed[pos] = src[i] | (etype[i] << 17);
}

// ---------------------------------------------------------------------------
// One warp per dst node, TWO edges per broadcast iteration (R12 best form).
// Scores are summed from the two per-half partials (one float2 load).
// ---------------------------------------------------------------------------
__global__ void __launch_bounds__(256)
gather_kernel(const float* __restrict__ rel, float* __restrict__ out, int N) {
    int node = (blockIdx.x * blockDim.x + threadIdx.x) >> 5;
    int lane = threadIdx.x & 31;
    if (node >= N) return;

    int beg = g_off[node], end = g_off[node + 1];
    float2 sdp = *(const float2*)&g_sdst2[node * 2];
    float sd = sdp.x + sdp.y;

    int hl = lane >> 4;          // which edge of the pair
    int c8 = lane & 15;          // col-octet (8 halves) this lane owns

    float acc[8];
#pragma unroll
    for (int j = 0; j < 8; j++) acc[j] = 0.f;
    float dsum = 0.f;
    const uint4* zh4 = (const uint4*)g_zh;   // 16 uint4 per row

    for (int base = beg; base < end; base += 32) {
        int idx = base + lane;
        float w = 0.f, exv = 0.f;
        int s = 0;
        if (idx < end) {
            int p = g_packed[idx];
            s = p & 131071;
            int et = p >> 17;
            float2 sp = *(const float2*)&g_ssrc2[s * 2];
            float v = sp.x + sp.y + sd;
            float e = v > 0.f ? v : 0.01f * v;
            exv = __expf(e);
            w = (et == 0 ? 0.f : __ldg(&rel[et])) * exv;
        }
        dsum += exv;
        int cnt = min(32, end - base);
        int npair = (cnt + 1) >> 1;
#pragma unroll 4
        for (int t = 0; t < npair; t++) {
            int e = 2 * t + hl;   // may be == cnt on odd tail -> w there is 0
            float wi = __shfl_sync(0xffffffffu, w, e);
            int   si = __shfl_sync(0xffffffffu, s, e);
            uint4 raw = zh4[(size_t)si * 16 + c8];
            float2 f0 = __half22float2(*(__half2*)&raw.x);
            float2 f1 = __half22float2(*(__half2*)&raw.y);
            float2 f2 = __half22float2(*(__half2*)&raw.z);
            float2 f3 = __half22float2(*(__half2*)&raw.w);
            acc[0] += wi * f0.x; acc[1] += wi * f0.y;
            acc[2] += wi * f1.x; acc[3] += wi * f1.y;
            acc[4] += wi * f2.x; acc[5] += wi * f2.y;
            acc[6] += wi * f3.x; acc[7] += wi * f3.y;
        }
    }

#pragma unroll
    for (int o = 16; o > 0; o >>= 1)
        dsum += __shfl_xor_sync(0xffffffffu, dsum, o);
#pragma unroll
    for (int j = 0; j < 8; j++)
        acc[j] += __shfl_xor_sync(0xffffffffu, acc[j], 16);

    float inv = dsum > 0.f ? __frcp_rn(dsum) : 0.f;
    if (lane < 16) {
        float4* o4 = (float4*)(out + (size_t)node * DOUT + c8 * 8);
        o4[0] = make_float4(acc[0] * inv, acc[1] * inv, acc[2] * inv, acc[3] * inv);
        o4[1] = make_float4(acc[4] * inv, acc[5] * inv, acc[6] * inv, acc[7] * inv);
    }
}

// ---------------------------------------------------------------------------
extern "C" void kernel_launch(void* const* d_in, const int* in_sizes, int n_in,
                              void* d_out, int out_size) {
    const float* h    = (const float*)d_in[0];
    const float* W    = (const float*)d_in[1];
    const float* attn = (const float*)d_in[2];
    const float* rel  = (const float*)d_in[3];
    const int*   src  = (const int*)d_in[4];
    const int*   dst  = (const int*)d_in[5];
    const int*   et   = (const int*)d_in[6];
    float* out = (float*)d_out;

    int N = in_sizes[0] / DOUT;
    int E = in_sizes[4];
    int nblk = (N + CHUNK - 1) / CHUNK;
    // smem: Ah/Al 128*AS + Wh/Wl 64*WS (bf16) + attn
    int smem_bytes = (2 * 128 * AS + 2 * 64 * WS) * 2 + 256 * 4;   // ~103KB -> 2 blocks/SM
    int gemm_grid = ((N + 127) / 128) * 2;

    // Lazy one-time creation of side stream + events (host objects only; made
    // on the uncaptured correctness call, reused under capture). If creation
    // fails (e.g. transient driver state), fall back to serial single-stream.
    static cudaStream_t s2 = nullptr;
    static cudaEvent_t evFork = nullptr, evJoin = nullptr;
    static bool tried = false, have_fork = false, attr_set = false;
    if (!tried) {
        tried = true;
        if (cudaStreamCreateWithFlags(&s2, cudaStreamNonBlocking) == cudaSuccess &&
            cudaEventCreateWithFlags(&evFork, cudaEventDisableTiming) == cudaSuccess &&
            cudaEventCreateWithFlags(&evJoin, cudaEventDisableTiming) == cudaSuccess) {
            have_fork = true;
        }
    }
    if (!attr_set) {
        cudaFuncSetAttribute(gemm_kernel, cudaFuncAttributeMaxDynamicSharedMemorySize, smem_bytes);
        attr_set = true;
    }

    if (have_fork) {
        // Fork: edge-index chain on s2, gemm on the main (capturing) stream.
        // gemm submitted 4th so ncu's fixed capture slot profiles it.
        cudaEventRecord(evFork, 0);
        cudaStreamWaitEvent(s2, evFork, 0);

        clear_cnt<<<(N + 255) / 256, 256, 0, s2>>>(N);
        hist_kernel<<<(E + 255) / 256, 256, 0, s2>>>(dst, E);
        scan_kernel<<<nblk, 256, 0, s2>>>(N);

        gemm_kernel<<<gemm_grid, 256, smem_bytes>>>(h, W, attn, N);

        scatter_kernel<<<(E + 255) / 256, 256, 0, s2>>>(src, dst, et, E);
        cudaEventRecord(evJoin, s2);

        cudaStreamWaitEvent(0, evJoin, 0);
    } else {
        clear_cnt<<<(N + 255) / 256, 256>>>(N);
        hist_kernel<<<(E + 255) / 256, 256>>>(dst, E);
        scan_kernel<<<nblk, 256>>>(N);
        gemm_kernel<<<gemm_grid, 256, smem_bytes>>>(h, W, attn, N);
        scatter_kernel<<<(E + 255) / 256, 256>>>(src, dst, et, E);
    }

    gather_kernel<<<(N * 32 + 255) / 256, 256>>>(rel, out, N);
}